// round 13
// baseline (speedup 1.0000x reference)
#include <cuda_runtime.h>
#include <cuda_fp16.h>
#include <math.h>
#include <stdint.h>

#define SEQ    4096
#define DIM    768
#define NH     12
#define HD     64
#define BATCH  2
#define MROWS  (BATCH*SEQ)
#define BHEADS (BATCH*NH)
#define QSCALE 0.18033688011112042f  /* 64^-0.5 * log2(e) */

// fp16 operands, hi-plane only everywhere
__device__ __half g_xh[(size_t)MROWS*DIM];
__device__ __half g_wqh[(size_t)DIM*DIM];
__device__ __half g_wkh[(size_t)DIM*DIM];
__device__ __half g_wvh[(size_t)DIM*DIM];
__device__ __half g_woh[(size_t)DIM*DIM];
__device__ __half g_qhi[(size_t)BHEADS*SEQ*HD];
__device__ __half g_khi[(size_t)BHEADS*SEQ*HD];
__device__ __half g_vhi[(size_t)BHEADS*SEQ*HD];
__device__ __half g_att[(size_t)MROWS*DIM];

// ---------------- helpers ----------------------------------------------------
__device__ __forceinline__ uint32_t smem_u32(const void* p){
    uint32_t a;
    asm("{ .reg .u64 t; cvta.to.shared.u64 t, %1; cvt.u32.u64 %0, t; }" : "=r"(a) : "l"(p));
    return a;
}
__device__ __forceinline__ void ldsm4(uint32_t* r, uint32_t a){
    asm volatile("ldmatrix.sync.aligned.m8n8.x4.shared.b16 {%0,%1,%2,%3}, [%4];"
        : "=r"(r[0]),"=r"(r[1]),"=r"(r[2]),"=r"(r[3]) : "r"(a));
}
__device__ __forceinline__ void ldsm4t(uint32_t* r, uint32_t a){
    asm volatile("ldmatrix.sync.aligned.m8n8.x4.trans.shared.b16 {%0,%1,%2,%3}, [%4];"
        : "=r"(r[0]),"=r"(r[1]),"=r"(r[2]),"=r"(r[3]) : "r"(a));
}
__device__ __forceinline__ void mma16816(float* c, const uint32_t* a, uint32_t b0, uint32_t b1){
    asm volatile("mma.sync.aligned.m16n8k16.row.col.f32.f16.f16.f32 "
        "{%0,%1,%2,%3}, {%4,%5,%6,%7}, {%8,%9}, {%0,%1,%2,%3};"
        : "+f"(c[0]),"+f"(c[1]),"+f"(c[2]),"+f"(c[3])
        : "r"(a[0]),"r"(a[1]),"r"(a[2]),"r"(a[3]), "r"(b0),"r"(b1));
}
__device__ __forceinline__ uint32_t h2ex2(uint32_t x){
    uint32_t y; asm("ex2.approx.f16x2 %0, %1;" : "=r"(y) : "r"(x)); return y;
}
__device__ __forceinline__ uint32_t pk2h(float a, float b){
    __half2 t = __floats2half2_rn(a, b);
    return *reinterpret_cast<uint32_t*>(&t);
}
#define CPA(d,s)   asm volatile("cp.async.cg.shared.global [%0], [%1], 16;" :: "r"((uint32_t)(d)), "l"(s) : "memory")
#define CPCOMMIT() asm volatile("cp.async.commit_group;" ::: "memory")
#define CPWAIT1()  asm volatile("cp.async.wait_group 1;" ::: "memory")
#define CPWAIT0()  asm volatile("cp.async.wait_group 0;" ::: "memory")

// =============================================================================
// input conversion: fp32 -> fp16 (hi only)
// =============================================================================
__global__ void conv_x(const float4* __restrict__ src, uint2* __restrict__ dst, int n4)
{
    int i = blockIdx.x*blockDim.x + threadIdx.x;
    if (i < n4){
        float4 f = src[i];
        dst[i] = make_uint2(pk2h(f.x, f.y), pk2h(f.z, f.w));
    }
}
__global__ void conv_w(const float4* __restrict__ wq, const float4* __restrict__ wk,
                       const float4* __restrict__ wv, const float4* __restrict__ wo, int n4)
{
    int i = blockIdx.x*blockDim.x + threadIdx.x;
    if (i >= n4) return;
    const float4* s;
    uint2* d;
    switch (blockIdx.y){
        case 0:  s = wq; d = (uint2*)g_wqh; break;
        case 1:  s = wk; d = (uint2*)g_wkh; break;
        case 2:  s = wv; d = (uint2*)g_wvh; break;
        default: s = wo; d = (uint2*)g_woh; break;
    }
    float4 f = s[i];
    d[i] = make_uint2(pk2h(f.x, f.y), pk2h(f.z, f.w));
}

// =============================================================================
// 1-MMA GEMM core: 128x128 CTA, 8 warps (2x4), k-chunk 64, 2-stage cp.async.
// smem per stage: A|B each [128][72] fp16 = 36864 B. 2 CTAs/SM.
// =============================================================================
#define GPE  72
#define ARR  (128*GPE*2)        /* 18432 B per array */
#define STG2 (2*ARR)            /* 36864 B per stage */
#define GEMM_SMEM (2*STG2)      /* 73728 B */

__device__ __forceinline__ void gemm_pf(
    uint32_t sb, int s, int c, int row, int half,
    const __half* Ah, const __half* Bh)
{
    uint32_t base = sb + s*STG2 + (uint32_t)(row*GPE + half)*2;
    const size_t g = (size_t)c*64 + half;
#pragma unroll
    for (int u = 0; u < 4; u++){
        CPA(base + 0*ARR + u*16, Ah + g + u*8);
        CPA(base + 1*ARR + u*16, Bh + g + u*8);
    }
}

__device__ __forceinline__ void gemm_compute(
    uint32_t sb, int s, int wm, int wn, int L, float acc[4][4][4])
{
    const uint32_t bA = sb + s*STG2, bB = bA + ARR;
#pragma unroll
    for (int ks = 0; ks < 4; ks++){
        uint32_t ahf[4][4];
        uint32_t aoff = (uint32_t)(wm + (L & 15))*(GPE*2) + ks*32 + (L >> 4)*16;
#pragma unroll
        for (int im=0; im<4; im++)
            ldsm4(ahf[im], bA + aoff + im*16*(GPE*2));
        uint32_t bhf[2][4];
        uint32_t boff = (uint32_t)(wn + (L & 7) + ((L>>4)&1)*8)*(GPE*2) + ks*32 + ((L>>3)&1)*16;
#pragma unroll
        for (int jn=0; jn<2; jn++)
            ldsm4(bhf[jn], bB + boff + jn*16*(GPE*2));
#pragma unroll
        for (int im=0; im<4; im++)
#pragma unroll
            for (int n8=0; n8<4; n8++){
                int jn = n8>>1, ss = (n8&1)*2;
                mma16816(acc[im][n8], ahf[im], bhf[jn][ss], bhf[jn][ss+1]);
            }
    }
}

__global__ __launch_bounds__(256,2)
void qkv_mma()
{
    extern __shared__ __half dsm[];
    const uint32_t sb = smem_u32(dsm);
    const int z = blockIdx.z;
    const __half* Bh = (z==0) ? g_wqh : (z==1) ? g_wkh : g_wvh;
    __half* outp = (z==0) ? g_qhi : (z==1) ? g_khi : g_vhi;

    const int tid = threadIdx.x, L = tid & 31, wid = tid >> 5;
    const int wm = (wid >> 2) * 64, wn = (wid & 3) * 32;
    const int m0 = blockIdx.x * 128, n0 = blockIdx.y * 128;
    const int row = tid >> 1, half = (tid & 1) * 32;

    const __half* Ah = g_xh + (size_t)(m0+row)*DIM;
    const __half* Bp = Bh + (size_t)(n0+row)*DIM;

    float acc[4][4][4];
#pragma unroll
    for (int i=0;i<4;i++)
#pragma unroll
        for (int j=0;j<4;j++)
#pragma unroll
            for (int e=0;e<4;e++) acc[i][j][e] = 0.f;

    gemm_pf(sb, 0, 0, row, half, Ah, Bp);
    CPCOMMIT();
    for (int c = 0; c < 12; c++){
        if (c < 11){ gemm_pf(sb, (c+1)&1, c+1, row, half, Ah, Bp); CPCOMMIT(); CPWAIT1(); }
        else CPWAIT0();
        __syncthreads();
        gemm_compute(sb, c&1, wm, wn, L, acc);
        __syncthreads();
    }

    const float qs = (z==0) ? QSCALE : 1.f;
#pragma unroll
    for (int im=0; im<4; im++){
        int r0 = m0 + wm + im*16 + (L>>2);
#pragma unroll
        for (int n8=0; n8<4; n8++){
            int col = n0 + wn + n8*8 + 2*(L&3);
            int head = col >> 6, d = col & 63;
#pragma unroll
            for (int hf2=0; hf2<2; hf2++){
                int m = r0 + hf2*8;
                int b = m >> 12, n = m & (SEQ-1);
                size_t a = ((size_t)(b*NH+head)*SEQ + n)*HD + d;
                *(uint32_t*)(outp + a) =
                    pk2h(acc[im][n8][hf2*2]*qs, acc[im][n8][hf2*2+1]*qs);
            }
        }
    }
}

__global__ __launch_bounds__(256,2)
void proj_mma(const float* __restrict__ bo, float* __restrict__ out)
{
    extern __shared__ __half dsm[];
    const uint32_t sb = smem_u32(dsm);
    const int tid = threadIdx.x, L = tid & 31, wid = tid >> 5;
    const int wm = (wid >> 2) * 64, wn = (wid & 3) * 32;
    const int m0 = blockIdx.x * 128, n0 = blockIdx.y * 128;
    const int row = tid >> 1, half = (tid & 1) * 32;

    const __half* Ah = g_att + (size_t)(m0+row)*DIM;
    const __half* Bh = g_woh + (size_t)(n0+row)*DIM;

    float acc[4][4][4];
#pragma unroll
    for (int i=0;i<4;i++)
#pragma unroll
        for (int j=0;j<4;j++)
#pragma unroll
            for (int e=0;e<4;e++) acc[i][j][e] = 0.f;

    gemm_pf(sb, 0, 0, row, half, Ah, Bh);
    CPCOMMIT();
    for (int c = 0; c < 12; c++){
        if (c < 11){ gemm_pf(sb, (c+1)&1, c+1, row, half, Ah, Bh); CPCOMMIT(); CPWAIT1(); }
        else CPWAIT0();
        __syncthreads();
        gemm_compute(sb, c&1, wm, wn, L, acc);
        __syncthreads();
    }

#pragma unroll
    for (int im=0; im<4; im++){
        int r0 = m0 + wm + im*16 + (L>>2);
#pragma unroll
        for (int n8=0; n8<4; n8++){
            int col = n0 + wn + n8*8 + 2*(L&3);
            float b0 = bo[col], b1 = bo[col+1];
            *(float2*)(out + (size_t)r0*DIM + col) =
                make_float2(acc[im][n8][0]+b0, acc[im][n8][1]+b1);
            *(float2*)(out + (size_t)(r0+8)*DIM + col) =
                make_float2(acc[im][n8][2]+b0, acc[im][n8][3]+b1);
        }
    }
}

// =============================================================================
// Attention: CTA = 128 q x 32 KV tiles of 128; 2 CTAs/SM.
// Q hi-only frags in 16 persistent registers. 3-stage cp.async pipeline,
// ONE __syncthreads per tile. Warp-staggered kv halves (odd warps process
// h=1 first) + exp interleaved into the PV kg loop: overlaps MUFU with HMMA.
// smem: 3 stages of K|V, each [128][72] fp16 = 110592 B.
// =============================================================================
#define KVP  72
#define AARR (128*KVP*2)        /* 18432 */
#define ASTG (2*AARR)           /* K|V per stage: 36864 */
#define ATT_SMEM (3*ASTG)       /* 110592 */

__device__ __forceinline__ void attn_pf(uint32_t sb, int s, int k0, int row, int half,
                                        size_t base)
{
    uint32_t d = sb + s*ASTG + (uint32_t)(row*KVP + half)*2;
    size_t g = base + (size_t)(k0+row)*HD + half;
#pragma unroll
    for (int u = 0; u < 4; u++){
        CPA(d + 0*AARR + u*16, g_khi + g + u*8);
        CPA(d + 1*AARR + u*16, g_vhi + g + u*8);
    }
}

__global__ __launch_bounds__(256,2)
void attn_mma()
{
    extern __shared__ __half dsm[];
    const uint32_t sb = smem_u32(dsm);
    const int tid = threadIdx.x, L = tid & 31, w = tid >> 5;
    const int bh = blockIdx.x, q0 = blockIdx.y * 128;
    const size_t base = (size_t)bh * SEQ * HD;
    const int row = tid >> 1, half = (tid & 1) * 32;
    const int hswap = w & 1;     // odd warps do kv-half 1 first

    // ---- Q tile via stage-0 smem -> 16 persistent register frags -----------
    uint32_t qhf[4][4];
    {
        const uint4* qh = (const uint4*)(g_qhi + base + (size_t)(q0+row)*HD + half);
        uint4* dh = (uint4*)(dsm + row*KVP + half);
#pragma unroll
        for (int i=0;i<4;i++) dh[i] = qh[i];
        __syncwarp();
        uint32_t aoffq = (uint32_t)(w*16 + (L & 15))*(KVP*2) + (L >> 4)*16;
#pragma unroll
        for (int dg=0; dg<4; dg++)
            ldsm4(qhf[dg], sb + aoffq + dg*32);
    }
    __syncthreads();   // everyone done using stage 0 as Q staging

    float o[8][4], osum[4];
#pragma unroll
    for (int f=0;f<8;f++)
#pragma unroll
        for (int e=0;e<4;e++) o[f][e] = 0.f;
#pragma unroll
    for (int e=0;e<4;e++) osum[e] = 0.f;

    const uint32_t ones = ((L>>2)==0) ? 0x3C003C00u : 0u;   // B-frag: col 0 = 1.0

    // prologue: prefetch tiles 0 and 1 into stages 0 and 1
    attn_pf(sb, 0, 0,   row, half, base); CPCOMMIT();
    attn_pf(sb, 1, 128, row, half, base); CPCOMMIT();

    int s_cur = 0, s_pf = 2;
    for (int t = 0; t < SEQ/128; t++) {
        if (t < 30) CPWAIT1(); else CPWAIT0();
        __syncthreads();   // tile t data visible to all; all warps done with tile t-1
        if (t < 30){ attn_pf(sb, s_pf, (t+2)*128, row, half, base); CPCOMMIT(); }

        const uint32_t sK = sb + s_cur*ASTG;
        const uint32_t sV = sK + AARR;

#pragma unroll
        for (int hh = 0; hh < 2; hh++){
            const int h = hh ^ hswap;      // stagger kv-half order across warps
            // ---- S = Q K^T over 64 kv cols (Q hi only) ----------------------
            float s[8][4];
#pragma unroll
            for (int f=0;f<8;f++)
#pragma unroll
                for (int e=0;e<4;e++) s[f][e] = 0.f;
#pragma unroll
            for (int dg=0; dg<4; dg++){
#pragma unroll
                for (int j=0; j<4; j++){
                    int jj = h*4 + j;
                    uint32_t boff = (uint32_t)(jj*16 + (L & 7) + ((L>>4)&1)*8)*(KVP*2)
                                  + dg*32 + ((L>>3)&1)*16;
                    uint32_t bh4[4];
                    ldsm4(bh4, sK + boff);
                    mma16816(s[2*j],   qhf[dg], bh4[0], bh4[1]);
                    mma16816(s[2*j+1], qhf[dg], bh4[2], bh4[3]);
                }
            }

            // ---- per-kg: exp2 (MUFU) interleaved with PV (HMMA+LDSM) --------
#pragma unroll
            for (int kg=0; kg<4; kg++){
                uint32_t phi[4];
                phi[0] = h2ex2(pk2h(s[2*kg][0],   s[2*kg][1]));
                phi[1] = h2ex2(pk2h(s[2*kg][2],   s[2*kg][3]));
                phi[2] = h2ex2(pk2h(s[2*kg+1][0], s[2*kg+1][1]));
                phi[3] = h2ex2(pk2h(s[2*kg+1][2], s[2*kg+1][3]));
#pragma unroll
                for (int j=0; j<4; j++){
                    uint32_t voff = (uint32_t)(h*64 + kg*16 + (L & 7) + ((L>>3)&1)*8)*(KVP*2)
                                  + j*32 + ((L>>4)&1)*16;
                    uint32_t vh4[4];
                    ldsm4t(vh4, sV + voff);
                    mma16816(o[2*j],   phi, vh4[0], vh4[1]);
                    mma16816(o[2*j+1], phi, vh4[2], vh4[3]);
                }
                mma16816(osum, phi, ones, ones);
            }
        }
        s_cur = (s_cur == 2) ? 0 : s_cur + 1;
        s_pf  = (s_pf  == 2) ? 0 : s_pf  + 1;
    }

    // ---- epilogue: l from osum col 0, normalize, store fp16 [b, n, dim] ----
    const int b = bh / NH, head = bh % NH;
    const float ls0 = __shfl_sync(0xffffffffu, osum[0], L & 0x1C);
    const float ls1 = __shfl_sync(0xffffffffu, osum[2], L & 0x1C);
    const float inv0 = 1.f / ls0, inv1 = 1.f / ls1;
    const int r0 = q0 + w*16 + (L>>2);
#pragma unroll
    for (int f=0;f<8;f++){
        int col = f*8 + 2*(L&3);
        size_t a0 = ((size_t)b*SEQ + r0)  *DIM + head*HD + col;
        size_t a1 = ((size_t)b*SEQ + r0+8)*DIM + head*HD + col;
        *(uint32_t*)(g_att + a0) = pk2h(o[f][0]*inv0, o[f][1]*inv0);
        *(uint32_t*)(g_att + a1) = pk2h(o[f][2]*inv1, o[f][3]*inv1);
    }
}

// -----------------------------------------------------------------------------
extern "C" void kernel_launch(void* const* d_in, const int* in_sizes, int n_in,
                              void* d_out, int out_size)
{
    const float* x  = (const float*)d_in[0];
    const float* wq = (const float*)d_in[1];
    const float* wk = (const float*)d_in[2];
    const float* wv = (const float*)d_in[3];
    const float* wo = (const float*)d_in[4];
    const float* bo = (const float*)d_in[5];
    float* out = (float*)d_out;
    (void)in_sizes; (void)n_in; (void)out_size;

    static __half* xh;
    cudaGetSymbolAddress((void**)&xh, g_xh);

    cudaFuncSetAttribute(qkv_mma,  cudaFuncAttributeMaxDynamicSharedMemorySize, GEMM_SMEM);
    cudaFuncSetAttribute(attn_mma, cudaFuncAttributeMaxDynamicSharedMemorySize, ATT_SMEM);
    cudaFuncSetAttribute(proj_mma, cudaFuncAttributeMaxDynamicSharedMemorySize, GEMM_SMEM);

    const int nx4 = MROWS*DIM/4, nw4 = DIM*DIM/4;
    conv_x<<<(nx4+255)/256, 256>>>((const float4*)x, (uint2*)xh, nx4);
    conv_w<<<dim3((nw4+255)/256, 4), 256>>>((const float4*)wq, (const float4*)wk,
                                            (const float4*)wv, (const float4*)wo, nw4);

    qkv_mma <<<dim3(MROWS/128, DIM/128, 3), 256, GEMM_SMEM>>>();
    attn_mma<<<dim3(BHEADS, SEQ/128),       256, ATT_SMEM>>>();
    proj_mma<<<dim3(MROWS/128, DIM/128),    256, GEMM_SMEM>>>(bo, out);
}

// round 14
// speedup vs baseline: 1.5631x; 1.5631x over previous
#include <cuda_runtime.h>
#include <cuda_fp16.h>
#include <math.h>
#include <stdint.h>

#define SEQ    4096
#define DIM    768
#define NH     12
#define HD     64
#define BATCH  2
#define MROWS  (BATCH*SEQ)
#define BHEADS (BATCH*NH)
#define QSCALE 0.18033688011112042f  /* 64^-0.5 * log2(e) */

// fp16 operands, hi-plane only everywhere
__device__ __half g_xh[(size_t)MROWS*DIM];
__device__ __half g_wqh[(size_t)DIM*DIM];
__device__ __half g_wkh[(size_t)DIM*DIM];
__device__ __half g_wvh[(size_t)DIM*DIM];
__device__ __half g_woh[(size_t)DIM*DIM];
__device__ __half g_qhi[(size_t)BHEADS*SEQ*HD];
__device__ __half g_khi[(size_t)BHEADS*SEQ*HD];
__device__ __half g_vhi[(size_t)BHEADS*SEQ*HD];
__device__ __half g_att[(size_t)MROWS*DIM];

// ---------------- helpers ----------------------------------------------------
__device__ __forceinline__ uint32_t smem_u32(const void* p){
    uint32_t a;
    asm("{ .reg .u64 t; cvta.to.shared.u64 t, %1; cvt.u32.u64 %0, t; }" : "=r"(a) : "l"(p));
    return a;
}
__device__ __forceinline__ void ldsm4(uint32_t* r, uint32_t a){
    asm volatile("ldmatrix.sync.aligned.m8n8.x4.shared.b16 {%0,%1,%2,%3}, [%4];"
        : "=r"(r[0]),"=r"(r[1]),"=r"(r[2]),"=r"(r[3]) : "r"(a));
}
__device__ __forceinline__ void ldsm4t(uint32_t* r, uint32_t a){
    asm volatile("ldmatrix.sync.aligned.m8n8.x4.trans.shared.b16 {%0,%1,%2,%3}, [%4];"
        : "=r"(r[0]),"=r"(r[1]),"=r"(r[2]),"=r"(r[3]) : "r"(a));
}
__device__ __forceinline__ void mma16816(float* c, const uint32_t* a, uint32_t b0, uint32_t b1){
    asm volatile("mma.sync.aligned.m16n8k16.row.col.f32.f16.f16.f32 "
        "{%0,%1,%2,%3}, {%4,%5,%6,%7}, {%8,%9}, {%0,%1,%2,%3};"
        : "+f"(c[0]),"+f"(c[1]),"+f"(c[2]),"+f"(c[3])
        : "r"(a[0]),"r"(a[1]),"r"(a[2]),"r"(a[3]), "r"(b0),"r"(b1));
}
__device__ __forceinline__ uint32_t h2ex2(uint32_t x){
    uint32_t y; asm("ex2.approx.f16x2 %0, %1;" : "=r"(y) : "r"(x)); return y;
}
__device__ __forceinline__ uint32_t pk2h(float a, float b){
    __half2 t = __floats2half2_rn(a, b);
    return *reinterpret_cast<uint32_t*>(&t);
}
#define CPA(d,s)   asm volatile("cp.async.cg.shared.global [%0], [%1], 16;" :: "r"((uint32_t)(d)), "l"(s) : "memory")
#define CPCOMMIT() asm volatile("cp.async.commit_group;" ::: "memory")
#define CPWAIT1()  asm volatile("cp.async.wait_group 1;" ::: "memory")
#define CPWAIT0()  asm volatile("cp.async.wait_group 0;" ::: "memory")

// =============================================================================
// input conversion: fp32 -> fp16 (hi only)
// =============================================================================
__global__ void conv_x(const float4* __restrict__ src, uint2* __restrict__ dst, int n4)
{
    int i = blockIdx.x*blockDim.x + threadIdx.x;
    if (i < n4){
        float4 f = src[i];
        dst[i] = make_uint2(pk2h(f.x, f.y), pk2h(f.z, f.w));
    }
}
__global__ void conv_w(const float4* __restrict__ wq, const float4* __restrict__ wk,
                       const float4* __restrict__ wv, const float4* __restrict__ wo, int n4)
{
    int i = blockIdx.x*blockDim.x + threadIdx.x;
    if (i >= n4) return;
    const float4* s;
    uint2* d;
    switch (blockIdx.y){
        case 0:  s = wq; d = (uint2*)g_wqh; break;
        case 1:  s = wk; d = (uint2*)g_wkh; break;
        case 2:  s = wv; d = (uint2*)g_wvh; break;
        default: s = wo; d = (uint2*)g_woh; break;
    }
    float4 f = s[i];
    d[i] = make_uint2(pk2h(f.x, f.y), pk2h(f.z, f.w));
}

// =============================================================================
// 1-MMA GEMM core: 128x128 CTA, 8 warps (2x4), k-chunk 64, 3-stage cp.async,
// ONE __syncthreads per chunk. smem: 3 stages of A|B = 110592 B. 2 CTAs/SM.
// =============================================================================
#define GPE  72
#define ARR  (128*GPE*2)        /* 18432 B per array */
#define STG2 (2*ARR)            /* 36864 B per stage */
#define GEMM_SMEM (3*STG2)      /* 110592 B */

__device__ __forceinline__ void gemm_pf(
    uint32_t sb, int s, int c, int row, int half,
    const __half* Ah, const __half* Bh)
{
    uint32_t base = sb + s*STG2 + (uint32_t)(row*GPE + half)*2;
    const size_t g = (size_t)c*64 + half;
#pragma unroll
    for (int u = 0; u < 4; u++){
        CPA(base + 0*ARR + u*16, Ah + g + u*8);
        CPA(base + 1*ARR + u*16, Bh + g + u*8);
    }
}

__device__ __forceinline__ void gemm_compute(
    uint32_t sb, int s, int wm, int wn, int L, float acc[4][4][4])
{
    const uint32_t bA = sb + s*STG2, bB = bA + ARR;
#pragma unroll
    for (int ks = 0; ks < 4; ks++){
        uint32_t ahf[4][4];
        uint32_t aoff = (uint32_t)(wm + (L & 15))*(GPE*2) + ks*32 + (L >> 4)*16;
#pragma unroll
        for (int im=0; im<4; im++)
            ldsm4(ahf[im], bA + aoff + im*16*(GPE*2));
        uint32_t bhf[2][4];
        uint32_t boff = (uint32_t)(wn + (L & 7) + ((L>>4)&1)*8)*(GPE*2) + ks*32 + ((L>>3)&1)*16;
#pragma unroll
        for (int jn=0; jn<2; jn++)
            ldsm4(bhf[jn], bB + boff + jn*16*(GPE*2));
#pragma unroll
        for (int im=0; im<4; im++)
#pragma unroll
            for (int n8=0; n8<4; n8++){
                int jn = n8>>1, ss = (n8&1)*2;
                mma16816(acc[im][n8], ahf[im], bhf[jn][ss], bhf[jn][ss+1]);
            }
    }
}

// shared 12-chunk mainloop with 3-stage pipeline, one sync per chunk
__device__ __forceinline__ void gemm_mainloop(
    uint32_t sb, int row, int half, int wm, int wn, int L,
    const __half* Ah, const __half* Bh, float acc[4][4][4])
{
    gemm_pf(sb, 0, 0, row, half, Ah, Bh); CPCOMMIT();
    gemm_pf(sb, 1, 1, row, half, Ah, Bh); CPCOMMIT();
    int s_cur = 0, s_pf = 2;
    for (int c = 0; c < 12; c++){
        if (c < 10) CPWAIT1(); else CPWAIT0();
        __syncthreads();   // chunk c visible; all warps done with chunk c-1
        if (c < 10){ gemm_pf(sb, s_pf, c+2, row, half, Ah, Bh); CPCOMMIT(); }
        gemm_compute(sb, s_cur, wm, wn, L, acc);
        s_cur = (s_cur == 2) ? 0 : s_cur + 1;
        s_pf  = (s_pf  == 2) ? 0 : s_pf  + 1;
    }
}

__global__ __launch_bounds__(256,2)
void qkv_mma()
{
    extern __shared__ __half dsm[];
    const uint32_t sb = smem_u32(dsm);
    const int z = blockIdx.z;
    const __half* Bh = (z==0) ? g_wqh : (z==1) ? g_wkh : g_wvh;
    __half* outp = (z==0) ? g_qhi : (z==1) ? g_khi : g_vhi;

    const int tid = threadIdx.x, L = tid & 31, wid = tid >> 5;
    const int wm = (wid >> 2) * 64, wn = (wid & 3) * 32;
    const int m0 = blockIdx.x * 128, n0 = blockIdx.y * 128;
    const int row = tid >> 1, half = (tid & 1) * 32;

    const __half* Ah = g_xh + (size_t)(m0+row)*DIM;
    const __half* Bp = Bh + (size_t)(n0+row)*DIM;

    float acc[4][4][4];
#pragma unroll
    for (int i=0;i<4;i++)
#pragma unroll
        for (int j=0;j<4;j++)
#pragma unroll
            for (int e=0;e<4;e++) acc[i][j][e] = 0.f;

    gemm_mainloop(sb, row, half, wm, wn, L, Ah, Bp, acc);

    const float qs = (z==0) ? QSCALE : 1.f;
#pragma unroll
    for (int im=0; im<4; im++){
        int r0 = m0 + wm + im*16 + (L>>2);
#pragma unroll
        for (int n8=0; n8<4; n8++){
            int col = n0 + wn + n8*8 + 2*(L&3);
            int head = col >> 6, d = col & 63;
#pragma unroll
            for (int hf2=0; hf2<2; hf2++){
                int m = r0 + hf2*8;
                int b = m >> 12, n = m & (SEQ-1);
                size_t a = ((size_t)(b*NH+head)*SEQ + n)*HD + d;
                *(uint32_t*)(outp + a) =
                    pk2h(acc[im][n8][hf2*2]*qs, acc[im][n8][hf2*2+1]*qs);
            }
        }
    }
}

__global__ __launch_bounds__(256,2)
void proj_mma(const float* __restrict__ bo, float* __restrict__ out)
{
    extern __shared__ __half dsm[];
    const uint32_t sb = smem_u32(dsm);
    const int tid = threadIdx.x, L = tid & 31, wid = tid >> 5;
    const int wm = (wid >> 2) * 64, wn = (wid & 3) * 32;
    const int m0 = blockIdx.x * 128, n0 = blockIdx.y * 128;
    const int row = tid >> 1, half = (tid & 1) * 32;

    const __half* Ah = g_att + (size_t)(m0+row)*DIM;
    const __half* Bh = g_woh + (size_t)(n0+row)*DIM;

    float acc[4][4][4];
#pragma unroll
    for (int i=0;i<4;i++)
#pragma unroll
        for (int j=0;j<4;j++)
#pragma unroll
            for (int e=0;e<4;e++) acc[i][j][e] = 0.f;

    gemm_mainloop(sb, row, half, wm, wn, L, Ah, Bh, acc);

#pragma unroll
    for (int im=0; im<4; im++){
        int r0 = m0 + wm + im*16 + (L>>2);
#pragma unroll
        for (int n8=0; n8<4; n8++){
            int col = n0 + wn + n8*8 + 2*(L&3);
            float b0 = bo[col], b1 = bo[col+1];
            *(float2*)(out + (size_t)r0*DIM + col) =
                make_float2(acc[im][n8][0]+b0, acc[im][n8][1]+b1);
            *(float2*)(out + (size_t)(r0+8)*DIM + col) =
                make_float2(acc[im][n8][2]+b0, acc[im][n8][3]+b1);
        }
    }
}

// =============================================================================
// Attention (EXACT R12): CTA = 128 q x 32 KV tiles of 128; 2 CTAs/SM.
// Q hi-only frags in 16 persistent registers. 3-stage cp.async pipeline,
// ONE __syncthreads per tile. S = 1 MMA, exp2.f16x2 burst, PV + ones-column.
// smem: 3 stages of K|V, each [128][72] fp16 = 110592 B.
// =============================================================================
#define KVP  72
#define AARR (128*KVP*2)        /* 18432 */
#define ASTG (2*AARR)           /* K|V per stage: 36864 */
#define ATT_SMEM (3*ASTG)       /* 110592 */

__device__ __forceinline__ void attn_pf(uint32_t sb, int s, int k0, int row, int half,
                                        size_t base)
{
    uint32_t d = sb + s*ASTG + (uint32_t)(row*KVP + half)*2;
    size_t g = base + (size_t)(k0+row)*HD + half;
#pragma unroll
    for (int u = 0; u < 4; u++){
        CPA(d + 0*AARR + u*16, g_khi + g + u*8);
        CPA(d + 1*AARR + u*16, g_vhi + g + u*8);
    }
}

__global__ __launch_bounds__(256,2)
void attn_mma()
{
    extern __shared__ __half dsm[];
    const uint32_t sb = smem_u32(dsm);
    const int tid = threadIdx.x, L = tid & 31, w = tid >> 5;
    const int bh = blockIdx.x, q0 = blockIdx.y * 128;
    const size_t base = (size_t)bh * SEQ * HD;
    const int row = tid >> 1, half = (tid & 1) * 32;

    // ---- Q tile via stage-0 smem -> 16 persistent register frags -----------
    uint32_t qhf[4][4];
    {
        const uint4* qh = (const uint4*)(g_qhi + base + (size_t)(q0+row)*HD + half);
        uint4* dh = (uint4*)(dsm + row*KVP + half);
#pragma unroll
        for (int i=0;i<4;i++) dh[i] = qh[i];
        __syncwarp();
        uint32_t aoffq = (uint32_t)(w*16 + (L & 15))*(KVP*2) + (L >> 4)*16;
#pragma unroll
        for (int dg=0; dg<4; dg++)
            ldsm4(qhf[dg], sb + aoffq + dg*32);
    }
    __syncthreads();   // everyone done using stage 0 as Q staging

    float o[8][4], osum[4];
#pragma unroll
    for (int f=0;f<8;f++)
#pragma unroll
        for (int e=0;e<4;e++) o[f][e] = 0.f;
#pragma unroll
    for (int e=0;e<4;e++) osum[e] = 0.f;

    const uint32_t ones = ((L>>2)==0) ? 0x3C003C00u : 0u;   // B-frag: col 0 = 1.0

    // prologue: prefetch tiles 0 and 1 into stages 0 and 1
    attn_pf(sb, 0, 0,   row, half, base); CPCOMMIT();
    attn_pf(sb, 1, 128, row, half, base); CPCOMMIT();

    int s_cur = 0, s_pf = 2;
    for (int t = 0; t < SEQ/128; t++) {
        if (t < 30) CPWAIT1(); else CPWAIT0();
        __syncthreads();   // tile t data visible to all; all warps done with tile t-1
        if (t < 30){ attn_pf(sb, s_pf, (t+2)*128, row, half, base); CPCOMMIT(); }

        const uint32_t sK = sb + s_cur*ASTG;
        const uint32_t sV = sK + AARR;

#pragma unroll
        for (int h = 0; h < 2; h++){
            // ---- S = Q K^T over 64 kv cols (Q hi only) ----------------------
            float s[8][4];
#pragma unroll
            for (int f=0;f<8;f++)
#pragma unroll
                for (int e=0;e<4;e++) s[f][e] = 0.f;
#pragma unroll
            for (int dg=0; dg<4; dg++){
#pragma unroll
                for (int j=0; j<4; j++){
                    int jj = h*4 + j;
                    uint32_t boff = (uint32_t)(jj*16 + (L & 7) + ((L>>4)&1)*8)*(KVP*2)
                                  + dg*32 + ((L>>3)&1)*16;
                    uint32_t bh4[4];
                    ldsm4(bh4, sK + boff);
                    mma16816(s[2*j],   qhf[dg], bh4[0], bh4[1]);
                    mma16816(s[2*j+1], qhf[dg], bh4[2], bh4[3]);
                }
            }

            // ---- P = exp2(S) in fp16x2 (monolithic burst) --------------------
            uint32_t phi[4][4];
#pragma unroll
            for (int kg=0; kg<4; kg++){
                phi[kg][0] = h2ex2(pk2h(s[2*kg][0],   s[2*kg][1]));
                phi[kg][1] = h2ex2(pk2h(s[2*kg][2],   s[2*kg][3]));
                phi[kg][2] = h2ex2(pk2h(s[2*kg+1][0], s[2*kg+1][1]));
                phi[kg][3] = h2ex2(pk2h(s[2*kg+1][2], s[2*kg+1][3]));
            }

            // ---- O += P V ; osum += P ones ----------------------------------
#pragma unroll
            for (int kg=0; kg<4; kg++){
#pragma unroll
                for (int j=0; j<4; j++){
                    uint32_t voff = (uint32_t)(h*64 + kg*16 + (L & 7) + ((L>>3)&1)*8)*(KVP*2)
                                  + j*32 + ((L>>4)&1)*16;
                    uint32_t vh4[4];
                    ldsm4t(vh4, sV + voff);
                    mma16816(o[2*j],   phi[kg], vh4[0], vh4[1]);
                    mma16816(o[2*j+1], phi[kg], vh4[2], vh4[3]);
                }
                mma16816(osum, phi[kg], ones, ones);
            }
        }
        s_cur = (s_cur == 2) ? 0 : s_cur + 1;
        s_pf  = (s_pf  == 2) ? 0 : s_pf  + 1;
    }

    // ---- epilogue: l from osum col 0, normalize, store fp16 [b, n, dim] ----
    const int b = bh / NH, head = bh % NH;
    const float ls0 = __shfl_sync(0xffffffffu, osum[0], L & 0x1C);
    const float ls1 = __shfl_sync(0xffffffffu, osum[2], L & 0x1C);
    const float inv0 = 1.f / ls0, inv1 = 1.f / ls1;
    const int r0 = q0 + w*16 + (L>>2);
#pragma unroll
    for (int f=0;f<8;f++){
        int col = f*8 + 2*(L&3);
        size_t a0 = ((size_t)b*SEQ + r0)  *DIM + head*HD + col;
        size_t a1 = ((size_t)b*SEQ + r0+8)*DIM + head*HD + col;
        *(uint32_t*)(g_att + a0) = pk2h(o[f][0]*inv0, o[f][1]*inv0);
        *(uint32_t*)(g_att + a1) = pk2h(o[f][2]*inv1, o[f][3]*inv1);
    }
}

// -----------------------------------------------------------------------------
extern "C" void kernel_launch(void* const* d_in, const int* in_sizes, int n_in,
                              void* d_out, int out_size)
{
    const float* x  = (const float*)d_in[0];
    const float* wq = (const float*)d_in[1];
    const float* wk = (const float*)d_in[2];
    const float* wv = (const float*)d_in[3];
    const float* wo = (const float*)d_in[4];
    const float* bo = (const float*)d_in[5];
    float* out = (float*)d_out;
    (void)in_sizes; (void)n_in; (void)out_size;

    static __half* xh;
    cudaGetSymbolAddress((void**)&xh, g_xh);

    cudaFuncSetAttribute(qkv_mma,  cudaFuncAttributeMaxDynamicSharedMemorySize, GEMM_SMEM);
    cudaFuncSetAttribute(attn_mma, cudaFuncAttributeMaxDynamicSharedMemorySize, ATT_SMEM);
    cudaFuncSetAttribute(proj_mma, cudaFuncAttributeMaxDynamicSharedMemorySize, GEMM_SMEM);

    const int nx4 = MROWS*DIM/4, nw4 = DIM*DIM/4;
    conv_x<<<(nx4+255)/256, 256>>>((const float4*)x, (uint2*)xh, nx4);
    conv_w<<<dim3((nw4+255)/256, 4), 256>>>((const float4*)wq, (const float4*)wk,
                                            (const float4*)wv, (const float4*)wo, nw4);

    qkv_mma <<<dim3(MROWS/128, DIM/128, 3), 256, GEMM_SMEM>>>();
    attn_mma<<<dim3(BHEADS, SEQ/128),       256, ATT_SMEM>>>();
    proj_mma<<<dim3(MROWS/128, DIM/128),    256, GEMM_SMEM>>>(bo, out);
}